// round 1
// baseline (speedup 1.0000x reference)
#include <cuda_runtime.h>
#include <math.h>

#define NB 2
#define NN 768
#define NEG08 0.8f
#define EPSV 1e-6f
#define FEPS 1e-12f

// ---------------- scratch (device globals; no allocation allowed) ----------
__device__ float g_qx[NB * 96 * NN];      // Qx   [b][c][d][n]
__device__ float g_sq[NB * NN];           // ||yf||^2 per point
__device__ float g_score[NB * NN * NN];   // 2*inner - sq[m]  (row n major)
__device__ float g_ksum[NB * 96 * NN];    // sum_k Ky  [b][c][d][n]
__device__ float g_vsum[NB * 96 * NN];    // sum_k Vy  [b][c][d][n]

// ---------------- kernel 1: Qx = cevn(vn_linear_leaky(x, Wq)) --------------
// 1 warp per point (lane = output channel o), 4 points per block.
__global__ void qx_kernel(const float* __restrict__ x,
                          const float* __restrict__ Wf,
                          const float* __restrict__ Wd) {
    __shared__ float sWf[32][32];   // [c][o] transposed
    __shared__ float sWd[32][32];
    __shared__ float xs[4][96];
    int tid = threadIdx.x;
    for (int i = tid; i < 1024; i += 128) {
        int o = i >> 5, c = i & 31;
        sWf[c][o] = Wf[i];
        sWd[c][o] = Wd[i];
    }
    int wid = tid >> 5, lane = tid & 31;
    int pt = blockIdx.x * 4 + wid;     // 0..1535
    int b = pt / NN, n = pt % NN;
    for (int e = lane; e < 96; e += 32)
        xs[wid][e] = x[(b * 96 + e) * NN + n];
    __syncthreads();

    float p[3] = {0.f, 0.f, 0.f}, dv[3] = {0.f, 0.f, 0.f};
#pragma unroll
    for (int c = 0; c < 32; c++) {
        float wf = sWf[c][lane], wd = sWd[c][lane];
#pragma unroll
        for (int d = 0; d < 3; d++) {
            float xv = xs[wid][c * 3 + d];
            p[d]  = fmaf(wf, xv, p[d]);
            dv[d] = fmaf(wd, xv, dv[d]);
        }
    }
    float dot = p[0] * dv[0] + p[1] * dv[1] + p[2] * dv[2];
    float dsq = dv[0] * dv[0] + dv[1] * dv[1] + dv[2] * dv[2];
    if (dot < 0.f) {
        float f = NEG08 * dot / (dsq + EPSV);
        p[0] -= f * dv[0]; p[1] -= f * dv[1]; p[2] -= f * dv[2];
    }
    float nsq = p[0] * p[0] + p[1] * p[1] + p[2] * p[2];
    float nrm = sqrtf(nsq);
    float chsq = nsq;
#pragma unroll
    for (int off = 16; off; off >>= 1)
        chsq += __shfl_xor_sync(0xffffffffu, chsq, off);
    float chn = sqrtf(chsq);
    float fac = (nrm / fmaxf(nrm, FEPS)) / fmaxf(chn, FEPS);
#pragma unroll
    for (int d = 0; d < 3; d++)
        g_qx[(b * 96 + lane * 3 + d) * NN + n] = p[d] * fac;
}

// ---------------- kernel 2a: per-point squared norms -----------------------
__global__ void sq_kernel(const float* __restrict__ y) {
    int i = blockIdx.x * 256 + threadIdx.x;
    if (i >= NB * NN) return;
    int b = i / NN, m = i % NN;
    float s = 0.f;
#pragma unroll 8
    for (int j = 0; j < 96; j++) {
        float v = y[(b * 96 + j) * NN + m];
        s = fmaf(v, v, s);
    }
    g_sq[i] = s;
}

// ---------------- kernel 2b: score[b][n][m] = 2*<yn,ym> - sq[m] ------------
// (the -sq[n] row constant cannot change per-row top-k ordering; dropped)
__global__ void gram_kernel(const float* __restrict__ y) {
    __shared__ float As[32][64];
    __shared__ float Bs[32][64];
    int b = blockIdx.z;
    int n0 = blockIdx.y * 64, m0 = blockIdx.x * 64;
    int tx = threadIdx.x, ty = threadIdx.y;
    int tid = ty * 16 + tx;
    float acc[4][4] = {};
    for (int jc = 0; jc < 96; jc += 32) {
        __syncthreads();
        for (int e = tid; e < 2048; e += 256) {
            int kk = e >> 6, r = e & 63;
            As[kk][r] = y[(b * 96 + jc + kk) * NN + n0 + r];
            Bs[kk][r] = y[(b * 96 + jc + kk) * NN + m0 + r];
        }
        __syncthreads();
#pragma unroll
        for (int kk = 0; kk < 32; kk++) {
            float4 a4 = *(const float4*)&As[kk][ty * 4];
            float4 b4 = *(const float4*)&Bs[kk][tx * 4];
            float av[4] = {a4.x, a4.y, a4.z, a4.w};
            float bv[4] = {b4.x, b4.y, b4.z, b4.w};
#pragma unroll
            for (int i = 0; i < 4; i++)
#pragma unroll
                for (int j = 0; j < 4; j++)
                    acc[i][j] = fmaf(av[i], bv[j], acc[i][j]);
        }
    }
#pragma unroll
    for (int i = 0; i < 4; i++) {
        int n = n0 + ty * 4 + i;
        float4 o;
        float* po = (float*)&o;
#pragma unroll
        for (int j = 0; j < 4; j++) {
            int m = m0 + tx * 4 + j;
            po[j] = 2.f * acc[i][j] - g_sq[b * NN + m];
        }
        *(float4*)&g_score[((size_t)(b * NN + n)) * NN + m0 + tx * 4] = o;
    }
}

// ---------------- kernel 3: top-16 + neighbor VN-linear K/V ----------------
// 1 block (128 thr) per (b,n). Phase A: iterative argmax top-16 (tie -> lowest
// index, matching lax.top_k). Phase B: warp w handles k = r*4+w over 4 rounds;
// lane = output channel o; accumulate Ksum (with cevn) and Vsum.
__global__ void knn_kv_kernel(const float* __restrict__ y,
                              const float* __restrict__ Wkf,
                              const float* __restrict__ Wkd,
                              const float* __restrict__ Wvf,
                              const float* __restrict__ Wvd) {
    __shared__ float s_score[NN];
    __shared__ float s_rv[128];
    __shared__ int   s_ri[128];
    __shared__ int   s_sel[16];
    __shared__ float s_yc[96];
    __shared__ float s_ynb[4][96];
    __shared__ float sWkf[64][32], sWkd[64][32], sWvf[64][32], sWvd[64][32];
    __shared__ float s_accK[4][96], s_accV[4][96];

    int tid = threadIdx.x;
    int blk = blockIdx.x;
    int b = blk / NN, n = blk % NN;

    for (int i = tid; i < 2048; i += 128) {
        int o = i >> 6, cin = i & 63;      // global W layout [o][cin]
        sWkf[cin][o] = Wkf[i];
        sWkd[cin][o] = Wkd[i];
        sWvf[cin][o] = Wvf[i];
        sWvd[cin][o] = Wvd[i];
    }
    for (int i = tid; i < NN; i += 128)
        s_score[i] = g_score[((size_t)(b * NN + n)) * NN + i];
    if (tid < 96) s_yc[tid] = y[(b * 96 + tid) * NN + n];
    __syncthreads();

    // ---- Phase A: top-16 ----
    for (int it = 0; it < 16; it++) {
        float bv = -INFINITY; int bi = NN;
        for (int i = tid; i < NN; i += 128) {
            float v = s_score[i];
            if (v > bv || (v == bv && i < bi)) { bv = v; bi = i; }
        }
        s_rv[tid] = bv; s_ri[tid] = bi;
        __syncthreads();
        for (int off = 64; off > 0; off >>= 1) {
            if (tid < off) {
                float v2 = s_rv[tid + off]; int i2 = s_ri[tid + off];
                if (v2 > s_rv[tid] || (v2 == s_rv[tid] && i2 < s_ri[tid])) {
                    s_rv[tid] = v2; s_ri[tid] = i2;
                }
            }
            __syncthreads();
        }
        if (tid == 0) { s_sel[it] = s_ri[0]; s_score[s_ri[0]] = -INFINITY; }
        __syncthreads();
    }

    // ---- Phase B: neighbor VN-linear ----
    int wid = tid >> 5, lane = tid & 31;
    float aK[3] = {0.f, 0.f, 0.f}, aV[3] = {0.f, 0.f, 0.f};
    for (int r = 0; r < 4; r++) {
        int m = s_sel[r * 4 + wid];
        __syncwarp();
        for (int e = lane; e < 96; e += 32)
            s_ynb[wid][e] = y[(b * 96 + e) * NN + m];
        __syncwarp();

        float Kp[3] = {0.f,0.f,0.f}, Kd[3] = {0.f,0.f,0.f};
        float Vp[3] = {0.f,0.f,0.f}, Vd[3] = {0.f,0.f,0.f};
        const float* yn = s_ynb[wid];
#pragma unroll 4
        for (int cin = 0; cin < 64; cin++) {
            float wkf = sWkf[cin][lane], wkd = sWkd[cin][lane];
            float wvf = sWvf[cin][lane], wvd = sWvd[cin][lane];
            int c3 = (cin & 31) * 3;
            bool diff = cin < 32;
#pragma unroll
            for (int d = 0; d < 3; d++) {
                float ctr = s_yc[c3 + d];
                float gv = diff ? (yn[c3 + d] - ctr) : ctr;
                Kp[d] = fmaf(wkf, gv, Kp[d]);
                Kd[d] = fmaf(wkd, gv, Kd[d]);
                Vp[d] = fmaf(wvf, gv, Vp[d]);
                Vd[d] = fmaf(wvd, gv, Vd[d]);
            }
        }
        // K: leaky + cevn
        float dot = Kp[0]*Kd[0] + Kp[1]*Kd[1] + Kp[2]*Kd[2];
        float dsq = Kd[0]*Kd[0] + Kd[1]*Kd[1] + Kd[2]*Kd[2];
        if (dot < 0.f) {
            float f = NEG08 * dot / (dsq + EPSV);
            Kp[0] -= f*Kd[0]; Kp[1] -= f*Kd[1]; Kp[2] -= f*Kd[2];
        }
        float nsq = Kp[0]*Kp[0] + Kp[1]*Kp[1] + Kp[2]*Kp[2];
        float nrm = sqrtf(nsq);
        float chsq = nsq;
#pragma unroll
        for (int off = 16; off; off >>= 1)
            chsq += __shfl_xor_sync(0xffffffffu, chsq, off);
        float chn = sqrtf(chsq);
        float fac = (nrm / fmaxf(nrm, FEPS)) / fmaxf(chn, FEPS);
        aK[0] += Kp[0]*fac; aK[1] += Kp[1]*fac; aK[2] += Kp[2]*fac;
        // V: leaky only
        float dotv = Vp[0]*Vd[0] + Vp[1]*Vd[1] + Vp[2]*Vd[2];
        float dsqv = Vd[0]*Vd[0] + Vd[1]*Vd[1] + Vd[2]*Vd[2];
        if (dotv < 0.f) {
            float f = NEG08 * dotv / (dsqv + EPSV);
            Vp[0] -= f*Vd[0]; Vp[1] -= f*Vd[1]; Vp[2] -= f*Vd[2];
        }
        aV[0] += Vp[0]; aV[1] += Vp[1]; aV[2] += Vp[2];
    }
#pragma unroll
    for (int d = 0; d < 3; d++) {
        s_accK[wid][lane * 3 + d] = aK[d];
        s_accV[wid][lane * 3 + d] = aV[d];
    }
    __syncthreads();
    if (tid < 96) {
        float ks = s_accK[0][tid] + s_accK[1][tid] + s_accK[2][tid] + s_accK[3][tid];
        float vs = s_accV[0][tid] + s_accV[1][tid] + s_accV[2][tid] + s_accV[3][tid];
        g_ksum[(b * 96 + tid) * NN + n] = ks;
        g_vsum[(b * 96 + tid) * NN + n] = vs;
    }
}

// ---------------- kernel 4: rank-1 softmax attention -----------------------
// row = b*96 + c*3 + d (192 rows). |t*K| <= 16/sqrt(96) -> raw expf is safe.
__global__ void attn_kernel(const float* __restrict__ x,
                            float* __restrict__ out) {
    __shared__ float Ks[NN], Vs[NN];
    int row = blockIdx.y;
    int tid = threadIdx.x;
    int n = blockIdx.x * 256 + tid;
    size_t base = (size_t)row * NN;
    for (int i = tid; i < NN; i += 256) {
        Ks[i] = g_ksum[base + i];
        Vs[i] = g_vsum[base + i];
    }
    __syncthreads();
    const float scale = 0.10206207262f;   // 1/sqrt(96)
    float t = g_qx[base + n] * scale;
    float den = 0.f, num = 0.f;
#pragma unroll 4
    for (int m = 0; m < NN; m++) {
        float e = __expf(t * Ks[m]);
        den += e;
        num = fmaf(e, Vs[m], num);
    }
    out[base + n] = x[base + n] + num / den;
}

// ---------------- launcher --------------------------------------------------
extern "C" void kernel_launch(void* const* d_in, const int* in_sizes, int n_in,
                              void* d_out, int out_size) {
    const float* x   = (const float*)d_in[0];
    const float* y   = (const float*)d_in[1];
    const float* Wqf = (const float*)d_in[2];
    const float* Wqd = (const float*)d_in[3];
    const float* Wkf = (const float*)d_in[4];
    const float* Wkd = (const float*)d_in[5];
    const float* Wvf = (const float*)d_in[6];
    const float* Wvd = (const float*)d_in[7];
    float* out = (float*)d_out;

    qx_kernel<<<384, 128>>>(x, Wqf, Wqd);
    sq_kernel<<<6, 256>>>(y);
    gram_kernel<<<dim3(12, 12, NB), dim3(16, 16)>>>(y);
    knn_kv_kernel<<<NB * NN, 128>>>(y, Wkf, Wkd, Wvf, Wvd);
    attn_kernel<<<dim3(3, 192), 256>>>(x, out);
}

// round 2
// speedup vs baseline: 3.9838x; 3.9838x over previous
#include <cuda_runtime.h>
#include <math.h>

#define NB 2
#define NN 768
#define NEG08 0.8f
#define EPSV 1e-6f
#define FEPS 1e-12f

// ---------------- scratch (device globals) ---------------------------------
__device__ float g_qx[NB * 96 * NN];        // Qx   [b][c][d][n]
__device__ float g_sq[NB * NN];             // ||yf||^2 per point
__device__ float g_score[NB * NN * NN];     // 2*inner - sq[m]
__device__ float g_mb[NB * NN * 12 * 32];   // m-side: [b][n][a][d][o], a={Kf,Kd,Vf,Vd}
__device__ float g_nb[NB * NN * 12 * 32];   // n-side (hi-lo transform), same layout
__device__ float g_ksum[NB * 96 * NN];      // sum_k Ky
__device__ float g_vsum[NB * 96 * NN];      // sum_k Vy

__constant__ float c_invf[15] = {
    1.0f, 1.0f, 0.5f, 1.6666666667e-1f, 4.1666666667e-2f, 8.3333333333e-3f,
    1.3888888889e-3f, 1.9841269841e-4f, 2.4801587302e-5f, 2.7557319224e-6f,
    2.7557319224e-7f, 2.5052108385e-8f, 2.0876756988e-9f, 1.6059043837e-10f,
    1.1470745598e-11f};

// ---------------- kernel 1: per-point precompute ----------------------------
// Qx = cevn(vn_leaky(x,Wq));  sq = ||y||^2;
// m-side: Wlo . y ; n-side: (Whi - Wlo) . y   for Kf,Kd,Vf,Vd.
// 1 warp per point (lane = out channel o), 4 points per block.
__global__ void pre_kernel(const float* __restrict__ x,
                           const float* __restrict__ y,
                           const float* __restrict__ Wqf,
                           const float* __restrict__ Wqd,
                           const float* __restrict__ Wkf,
                           const float* __restrict__ Wkd,
                           const float* __restrict__ Wvf,
                           const float* __restrict__ Wvd) {
    __shared__ float sQf[32][32], sQd[32][32];     // [cin][o]
    __shared__ float sm[4][32][32], sn[4][32][32]; // [a][cin][o]
    __shared__ float xs[4][96], ys[4][96];
    int tid = threadIdx.x;
    for (int i = tid; i < 1024; i += 128) {
        int o = i >> 5, c = i & 31;
        sQf[c][o] = Wqf[i];
        sQd[c][o] = Wqd[i];
    }
    const float* Wkv[4] = {Wkf, Wkd, Wvf, Wvd};
#pragma unroll
    for (int a = 0; a < 4; a++) {
        const float* W = Wkv[a];
        for (int i = tid; i < 1024; i += 128) {
            int o = i >> 5, c = i & 31;
            float lo = W[o * 64 + c], hi = W[o * 64 + 32 + c];
            sm[a][c][o] = lo;
            sn[a][c][o] = hi - lo;
        }
    }
    int wid = tid >> 5, lane = tid & 31;
    int pt = blockIdx.x * 4 + wid;
    int b = pt / NN, n = pt % NN;
    for (int e = lane; e < 96; e += 32) {
        xs[wid][e] = x[(b * 96 + e) * NN + n];
        ys[wid][e] = y[(b * 96 + e) * NN + n];
    }
    __syncthreads();

    float qp[3] = {}, qd[3] = {};
    float am[4][3] = {}, an[4][3] = {};
#pragma unroll
    for (int c = 0; c < 32; c++) {
        float wqf = sQf[c][lane], wqd = sQd[c][lane];
#pragma unroll
        for (int d = 0; d < 3; d++) {
            float xv = xs[wid][c * 3 + d];
            float yv = ys[wid][c * 3 + d];
            qp[d] = fmaf(wqf, xv, qp[d]);
            qd[d] = fmaf(wqd, xv, qd[d]);
#pragma unroll
            for (int a = 0; a < 4; a++) {
                am[a][d] = fmaf(sm[a][c][lane], yv, am[a][d]);
                an[a][d] = fmaf(sn[a][c][lane], yv, an[a][d]);
            }
        }
    }
    // Q nonlinearity + cevn
    float dot = qp[0] * qd[0] + qp[1] * qd[1] + qp[2] * qd[2];
    float dsq = qd[0] * qd[0] + qd[1] * qd[1] + qd[2] * qd[2];
    if (dot < 0.f) {
        float f = NEG08 * dot / (dsq + EPSV);
        qp[0] -= f * qd[0]; qp[1] -= f * qd[1]; qp[2] -= f * qd[2];
    }
    float nsq = qp[0] * qp[0] + qp[1] * qp[1] + qp[2] * qp[2];
    float nrm = sqrtf(nsq);
    float chsq = nsq;
#pragma unroll
    for (int off = 16; off; off >>= 1)
        chsq += __shfl_xor_sync(0xffffffffu, chsq, off);
    float chn = sqrtf(chsq);
    float fac = (nrm / fmaxf(nrm, FEPS)) / fmaxf(chn, FEPS);
#pragma unroll
    for (int d = 0; d < 3; d++)
        g_qx[(b * 96 + lane * 3 + d) * NN + n] = qp[d] * fac;

    // sq
    float sqv = 0.f;
    for (int e = lane; e < 96; e += 32) {
        float v = ys[wid][e];
        sqv = fmaf(v, v, sqv);
    }
#pragma unroll
    for (int off = 16; off; off >>= 1)
        sqv += __shfl_xor_sync(0xffffffffu, sqv, off);
    if (lane == 0) g_sq[b * NN + n] = sqv;

    // store transformed vectors, coalesced per (a,d)
    size_t base = (size_t)(b * NN + n) * 12 * 32;
#pragma unroll
    for (int a = 0; a < 4; a++)
#pragma unroll
        for (int d = 0; d < 3; d++) {
            g_mb[base + (a * 3 + d) * 32 + lane] = am[a][d];
            g_nb[base + (a * 3 + d) * 32 + lane] = an[a][d];
        }
}

// ---------------- kernel 2: score[b][n][m] = 2*<yn,ym> - sq[m] -------------
__global__ void gram_kernel(const float* __restrict__ y) {
    __shared__ float As[32][64];
    __shared__ float Bs[32][64];
    int b = blockIdx.z;
    int n0 = blockIdx.y * 64, m0 = blockIdx.x * 64;
    int tx = threadIdx.x, ty = threadIdx.y;
    int tid = ty * 16 + tx;
    float acc[4][4] = {};
    for (int jc = 0; jc < 96; jc += 32) {
        __syncthreads();
        for (int e = tid; e < 2048; e += 256) {
            int kk = e >> 6, r = e & 63;
            As[kk][r] = y[(b * 96 + jc + kk) * NN + n0 + r];
            Bs[kk][r] = y[(b * 96 + jc + kk) * NN + m0 + r];
        }
        __syncthreads();
#pragma unroll
        for (int kk = 0; kk < 32; kk++) {
            float4 a4 = *(const float4*)&As[kk][ty * 4];
            float4 b4 = *(const float4*)&Bs[kk][tx * 4];
            float av[4] = {a4.x, a4.y, a4.z, a4.w};
            float bv[4] = {b4.x, b4.y, b4.z, b4.w};
#pragma unroll
            for (int i = 0; i < 4; i++)
#pragma unroll
                for (int j = 0; j < 4; j++)
                    acc[i][j] = fmaf(av[i], bv[j], acc[i][j]);
        }
    }
#pragma unroll
    for (int i = 0; i < 4; i++) {
        int n = n0 + ty * 4 + i;
        float4 o;
        float* po = (float*)&o;
#pragma unroll
        for (int j = 0; j < 4; j++) {
            int m = m0 + tx * 4 + j;
            po[j] = 2.f * acc[i][j] - g_sq[b * NN + m];
        }
        *(float4*)&g_score[((size_t)(b * NN + n)) * NN + m0 + tx * 4] = o;
    }
}

// ---------------- kernel 3: top-16 + neighbor K/V sums ----------------------
// 1 block (128 thr) per (b,n). Scores live in registers (6/thread).
__global__ void knn_kernel() {
    __shared__ int s_sel[16];
    __shared__ unsigned s_wm[4];
    __shared__ int s_wi[4];
    __shared__ float s_accK[4][96], s_accV[4][96];

    int tid = threadIdx.x, blk = blockIdx.x;
    int b = blk / NN, n = blk % NN;
    int wid = tid >> 5, lane = tid & 31;

    const float* srow = g_score + (size_t)(b * NN + n) * NN;
    unsigned mono_[6];
#pragma unroll
    for (int j = 0; j < 6; j++) {
        unsigned u = __float_as_uint(srow[tid + j * 128]);
        mono_[j] = (u & 0x80000000u) ? ~u : (u | 0x80000000u);
    }

    // ---- top-16: exact value, exact lowest-index tie-break ----
    for (int it = 0; it < 16; it++) {
        unsigned bm = mono_[0];
        int bj = 0;
#pragma unroll
        for (int j = 1; j < 6; j++)
            if (mono_[j] > bm) { bm = mono_[j]; bj = j; }
        int bidx = tid + bj * 128;
        unsigned wm = __reduce_max_sync(0xffffffffu, bm);
        unsigned cand = (bm == wm) ? (unsigned)bidx : 1024u;
        unsigned wmin = __reduce_min_sync(0xffffffffu, cand);
        if (lane == 0) { s_wm[wid] = wm; s_wi[wid] = (int)wmin; }
        __syncthreads();
        unsigned Bv = s_wm[0];
        int Bi = s_wi[0];
#pragma unroll
        for (int w = 1; w < 4; w++) {
            unsigned v2 = s_wm[w];
            int i2 = s_wi[w];
            if (v2 > Bv || (v2 == Bv && i2 < Bi)) { Bv = v2; Bi = i2; }
        }
        if (tid == 0) s_sel[it] = Bi;
#pragma unroll
        for (int j = 0; j < 6; j++)
            if (tid + j * 128 == Bi) mono_[j] = 0u;
        __syncthreads();
    }

    // ---- neighbor K/V: warp w handles neighbors r*4+w ----
    float nbv[12];
    const float* nbase = g_nb + (size_t)(b * NN + n) * 12 * 32;
#pragma unroll
    for (int q = 0; q < 12; q++) nbv[q] = nbase[q * 32 + lane];

    float aK[3] = {}, aV[3] = {};
    for (int r = 0; r < 4; r++) {
        int m = s_sel[r * 4 + wid];
        const float* mbase = g_mb + (size_t)(b * NN + m) * 12 * 32;
        float mb[12];
#pragma unroll
        for (int q = 0; q < 12; q++) mb[q] = mbase[q * 32 + lane];

        float Kp[3], Kd[3], Vp[3], Vd[3];
#pragma unroll
        for (int d = 0; d < 3; d++) {
            Kp[d] = mb[0 + d] + nbv[0 + d];
            Kd[d] = mb[3 + d] + nbv[3 + d];
            Vp[d] = mb[6 + d] + nbv[6 + d];
            Vd[d] = mb[9 + d] + nbv[9 + d];
        }
        // K: leaky + cevn
        float dot = Kp[0] * Kd[0] + Kp[1] * Kd[1] + Kp[2] * Kd[2];
        float dsq = Kd[0] * Kd[0] + Kd[1] * Kd[1] + Kd[2] * Kd[2];
        if (dot < 0.f) {
            float f = NEG08 * dot / (dsq + EPSV);
            Kp[0] -= f * Kd[0]; Kp[1] -= f * Kd[1]; Kp[2] -= f * Kd[2];
        }
        float nsq = Kp[0] * Kp[0] + Kp[1] * Kp[1] + Kp[2] * Kp[2];
        float nrm = sqrtf(nsq);
        float chsq = nsq;
#pragma unroll
        for (int off = 16; off; off >>= 1)
            chsq += __shfl_xor_sync(0xffffffffu, chsq, off);
        float chn = sqrtf(chsq);
        float fac = (nrm / fmaxf(nrm, FEPS)) / fmaxf(chn, FEPS);
        aK[0] += Kp[0] * fac; aK[1] += Kp[1] * fac; aK[2] += Kp[2] * fac;
        // V: leaky only
        float dotv = Vp[0] * Vd[0] + Vp[1] * Vd[1] + Vp[2] * Vd[2];
        float dsqv = Vd[0] * Vd[0] + Vd[1] * Vd[1] + Vd[2] * Vd[2];
        if (dotv < 0.f) {
            float f = NEG08 * dotv / (dsqv + EPSV);
            Vp[0] -= f * Vd[0]; Vp[1] -= f * Vd[1]; Vp[2] -= f * Vd[2];
        }
        aV[0] += Vp[0]; aV[1] += Vp[1]; aV[2] += Vp[2];
    }
#pragma unroll
    for (int d = 0; d < 3; d++) {
        s_accK[wid][lane * 3 + d] = aK[d];
        s_accV[wid][lane * 3 + d] = aV[d];
    }
    __syncthreads();
    if (tid < 96) {
        float ks = s_accK[0][tid] + s_accK[1][tid] + s_accK[2][tid] + s_accK[3][tid];
        float vs = s_accV[0][tid] + s_accV[1][tid] + s_accV[2][tid] + s_accV[3][tid];
        g_ksum[(b * 96 + tid) * NN + n] = ks;
        g_vsum[(b * 96 + tid) * NN + n] = vs;
    }
}

// ---------------- kernel 4: rank-1 softmax via Taylor moments ---------------
// |t*K| <= 16/sqrt(96) = 1.633 -> order-14 Taylor, remainder < 6e-9 absolute.
__global__ void attn_kernel(const float* __restrict__ x,
                            float* __restrict__ out) {
    __shared__ float sMo[15], sGo[15];
    __shared__ float s_part[8][30];
    int row = blockIdx.x, tid = threadIdx.x;  // 256 threads, rows = 192
    size_t base = (size_t)row * NN;
    int wid = tid >> 5, lane = tid & 31;

    float Kv[3], Vv[3];
#pragma unroll
    for (int j = 0; j < 3; j++) {
        int m = tid + j * 256;
        Kv[j] = g_ksum[base + m];
        Vv[j] = g_vsum[base + m];
    }
    float M[15], G[15];
    float p0 = 1.f, p1 = 1.f, p2 = 1.f;
#pragma unroll
    for (int jj = 0; jj < 15; jj++) {
        M[jj] = (p0 + p1) + p2;
        G[jj] = fmaf(Vv[0], p0, fmaf(Vv[1], p1, Vv[2] * p2));
        p0 *= Kv[0]; p1 *= Kv[1]; p2 *= Kv[2];
    }
#pragma unroll
    for (int jj = 0; jj < 15; jj++) {
#pragma unroll
        for (int off = 16; off; off >>= 1) {
            M[jj] += __shfl_xor_sync(0xffffffffu, M[jj], off);
            G[jj] += __shfl_xor_sync(0xffffffffu, G[jj], off);
        }
    }
    if (lane == 0) {
#pragma unroll
        for (int jj = 0; jj < 15; jj++) {
            s_part[wid][jj] = M[jj];
            s_part[wid][15 + jj] = G[jj];
        }
    }
    __syncthreads();
    if (tid < 15) {
        float s = 0.f;
#pragma unroll
        for (int w = 0; w < 8; w++) s += s_part[w][tid];
        sMo[tid] = s * c_invf[tid];
    } else if (tid >= 32 && tid < 47) {
        int jj = tid - 32;
        float s = 0.f;
#pragma unroll
        for (int w = 0; w < 8; w++) s += s_part[w][15 + jj];
        sGo[jj] = s * c_invf[jj];
    }
    __syncthreads();

    float cM[15], cG[15];
#pragma unroll
    for (int jj = 0; jj < 15; jj++) { cM[jj] = sMo[jj]; cG[jj] = sGo[jj]; }

    const float scale = 0.10206207262f;  // 1/sqrt(96)
#pragma unroll
    for (int j2 = 0; j2 < 3; j2++) {
        int m = tid + j2 * 256;
        float t = g_qx[base + m] * scale;
        float den = cM[14], num = cG[14];
#pragma unroll
        for (int jj = 13; jj >= 0; jj--) {
            den = fmaf(den, t, cM[jj]);
            num = fmaf(num, t, cG[jj]);
        }
        out[base + m] = x[base + m] + num / den;
    }
}

// ---------------- launcher --------------------------------------------------
extern "C" void kernel_launch(void* const* d_in, const int* in_sizes, int n_in,
                              void* d_out, int out_size) {
    const float* x   = (const float*)d_in[0];
    const float* y   = (const float*)d_in[1];
    const float* Wqf = (const float*)d_in[2];
    const float* Wqd = (const float*)d_in[3];
    const float* Wkf = (const float*)d_in[4];
    const float* Wkd = (const float*)d_in[5];
    const float* Wvf = (const float*)d_in[6];
    const float* Wvd = (const float*)d_in[7];
    float* out = (float*)d_out;

    pre_kernel<<<384, 128>>>(x, y, Wqf, Wqd, Wkf, Wkd, Wvf, Wvd);
    gram_kernel<<<dim3(12, 12, NB), dim3(16, 16)>>>(y);
    knn_kernel<<<NB * NN, 128>>>();
    attn_kernel<<<192, 256>>>(x, out);
}

// round 3
// speedup vs baseline: 7.2970x; 1.8317x over previous
#include <cuda_runtime.h>
#include <math.h>

#define NB 2
#define NN 768
#define NEG08 0.8f
#define EPSV 1e-6f
#define FEPS 1e-12f

// ---------------- scratch (device globals) ---------------------------------
__device__ float g_qx[NB * 96 * NN];        // Qx   [b][c][d][n] (row = b*96+c*3+d)
__device__ float g_sq[NB * NN];             // ||yf||^2 per point
__device__ float g_score[NB * NN * NN];     // 2*inner - sq[m]
__device__ float g_mb[NB * NN * 32 * 12];   // m-side: [point][o][12] (Kf,Kd,Vf,Vd x d)
__device__ float g_nb[NB * NN * 32 * 12];   // n-side (hi-lo transform), same layout
__device__ float g_ksum[NB * 96 * NN];      // sum_k Ky   [row][n]
__device__ float g_vsum[NB * 96 * NN];      // sum_k Vy   [row][n]
__device__ float g_part[192 * 2 * 32];      // moment partials [row][half][30]

__constant__ float c_invf[15] = {
    1.0f, 1.0f, 0.5f, 1.6666666667e-1f, 4.1666666667e-2f, 8.3333333333e-3f,
    1.3888888889e-3f, 1.9841269841e-4f, 2.4801587302e-5f, 2.7557319224e-6f,
    2.7557319224e-7f, 2.5052108385e-8f, 2.0876756988e-9f, 1.6059043837e-10f,
    1.1470745598e-11f};

// ---------------- kernel 1: per-point precompute ----------------------------
__global__ void pre_kernel(const float* __restrict__ x,
                           const float* __restrict__ y,
                           const float* __restrict__ Wqf,
                           const float* __restrict__ Wqd,
                           const float* __restrict__ Wkf,
                           const float* __restrict__ Wkd,
                           const float* __restrict__ Wvf,
                           const float* __restrict__ Wvd) {
    __shared__ float2 sQ[32][32];       // [cin][o] = {Wqf, Wqd}
    __shared__ float4 sM[32][32];       // m-side {Kf,Kd,Vf,Vd}
    __shared__ float4 sN[32][32];       // n-side (hi - lo)
    __shared__ float xs[4][96], ys[4][96];
    int tid = threadIdx.x;
    for (int i = tid; i < 1024; i += 128) {
        int o = i >> 5, c = i & 31;
        sQ[c][o] = make_float2(Wqf[i], Wqd[i]);
        float kfl = Wkf[o * 64 + c], kdl = Wkd[o * 64 + c];
        float vfl = Wvf[o * 64 + c], vdl = Wvd[o * 64 + c];
        sM[c][o] = make_float4(kfl, kdl, vfl, vdl);
        sN[c][o] = make_float4(Wkf[o * 64 + 32 + c] - kfl,
                               Wkd[o * 64 + 32 + c] - kdl,
                               Wvf[o * 64 + 32 + c] - vfl,
                               Wvd[o * 64 + 32 + c] - vdl);
    }
    int wid = tid >> 5, lane = tid & 31;
    int pt = blockIdx.x * 4 + wid;
    int b = pt / NN, n = pt % NN;
    for (int e = lane; e < 96; e += 32) {
        xs[wid][e] = x[(b * 96 + e) * NN + n];
        ys[wid][e] = y[(b * 96 + e) * NN + n];
    }
    __syncthreads();

    float qp[3] = {}, qd[3] = {};
    float am[4][3] = {}, an[4][3] = {};
#pragma unroll
    for (int c = 0; c < 32; c++) {
        float2 q = sQ[c][lane];
        float4 mv = sM[c][lane];
        float4 nv = sN[c][lane];
        float mvv[4] = {mv.x, mv.y, mv.z, mv.w};
        float nvv[4] = {nv.x, nv.y, nv.z, nv.w};
#pragma unroll
        for (int d = 0; d < 3; d++) {
            float xv = xs[wid][c * 3 + d];
            float yv = ys[wid][c * 3 + d];
            qp[d] = fmaf(q.x, xv, qp[d]);
            qd[d] = fmaf(q.y, xv, qd[d]);
#pragma unroll
            for (int a = 0; a < 4; a++) {
                am[a][d] = fmaf(mvv[a], yv, am[a][d]);
                an[a][d] = fmaf(nvv[a], yv, an[a][d]);
            }
        }
    }
    // Q nonlinearity + cevn
    float dot = qp[0] * qd[0] + qp[1] * qd[1] + qp[2] * qd[2];
    float dsq = qd[0] * qd[0] + qd[1] * qd[1] + qd[2] * qd[2];
    if (dot < 0.f) {
        float f = NEG08 * dot / (dsq + EPSV);
        qp[0] -= f * qd[0]; qp[1] -= f * qd[1]; qp[2] -= f * qd[2];
    }
    float nsq = qp[0] * qp[0] + qp[1] * qp[1] + qp[2] * qp[2];
    float nrm = sqrtf(nsq);
    float chsq = nsq;
#pragma unroll
    for (int off = 16; off; off >>= 1)
        chsq += __shfl_xor_sync(0xffffffffu, chsq, off);
    float chn = sqrtf(chsq);
    float fac = (nrm / fmaxf(nrm, FEPS)) / fmaxf(chn, FEPS);
#pragma unroll
    for (int d = 0; d < 3; d++)
        g_qx[(b * 96 + lane * 3 + d) * NN + n] = qp[d] * fac;

    // sq
    float sqv = 0.f;
    for (int e = lane; e < 96; e += 32) {
        float v = ys[wid][e];
        sqv = fmaf(v, v, sqv);
    }
#pragma unroll
    for (int off = 16; off; off >>= 1)
        sqv += __shfl_xor_sync(0xffffffffu, sqv, off);
    if (lane == 0) g_sq[b * NN + n] = sqv;

    // transformed vectors: [point][o][12] as 3 float4s (coalesced warp-wide)
    size_t base = ((size_t)(b * NN + n) * 32 + lane) * 12;
    float4* mb4 = (float4*)(g_mb + base);
    float4* nb4 = (float4*)(g_nb + base);
    mb4[0] = make_float4(am[0][0], am[0][1], am[0][2], am[1][0]);
    mb4[1] = make_float4(am[1][1], am[1][2], am[2][0], am[2][1]);
    mb4[2] = make_float4(am[2][2], am[3][0], am[3][1], am[3][2]);
    nb4[0] = make_float4(an[0][0], an[0][1], an[0][2], an[1][0]);
    nb4[1] = make_float4(an[1][1], an[1][2], an[2][0], an[2][1]);
    nb4[2] = make_float4(an[2][2], an[3][0], an[3][1], an[3][2]);
}

// ---------------- kernel 2: score[b][n][m] = 2*<yn,ym> - sq[m] -------------
__global__ void gram_kernel(const float* __restrict__ y) {
    __shared__ float As[32][64];
    __shared__ float Bs[32][64];
    int b = blockIdx.z;
    int n0 = blockIdx.y * 64, m0 = blockIdx.x * 64;
    int tx = threadIdx.x, ty = threadIdx.y;
    int tid = ty * 16 + tx;
    float acc[4][4] = {};
    for (int jc = 0; jc < 96; jc += 32) {
        __syncthreads();
        for (int e = tid; e < 2048; e += 256) {
            int kk = e >> 6, r = e & 63;
            As[kk][r] = y[(b * 96 + jc + kk) * NN + n0 + r];
            Bs[kk][r] = y[(b * 96 + jc + kk) * NN + m0 + r];
        }
        __syncthreads();
#pragma unroll
        for (int kk = 0; kk < 32; kk++) {
            float4 a4 = *(const float4*)&As[kk][ty * 4];
            float4 b4 = *(const float4*)&Bs[kk][tx * 4];
            float av[4] = {a4.x, a4.y, a4.z, a4.w};
            float bv[4] = {b4.x, b4.y, b4.z, b4.w};
#pragma unroll
            for (int i = 0; i < 4; i++)
#pragma unroll
                for (int j = 0; j < 4; j++)
                    acc[i][j] = fmaf(av[i], bv[j], acc[i][j]);
        }
    }
#pragma unroll
    for (int i = 0; i < 4; i++) {
        int n = n0 + ty * 4 + i;
        float4 o;
        float* po = (float*)&o;
#pragma unroll
        for (int j = 0; j < 4; j++) {
            int m = m0 + tx * 4 + j;
            po[j] = 2.f * acc[i][j] - g_sq[b * NN + m];
        }
        *(float4*)&g_score[((size_t)(b * NN + n)) * NN + m0 + tx * 4] = o;
    }
}

// ---------------- kernel 3: warp-per-point top-16 + K/V sums ---------------
// grid 384 x 128thr; warp w of block handles point blockIdx*4+w. No barriers.
__global__ void knn_kernel() {
    int tid = threadIdx.x;
    int wid = tid >> 5, lane = tid & 31;
    int pt = blockIdx.x * 4 + wid;
    int b = pt / NN, n = pt % NN;

    // load 24 scores per lane as float4; global idx of mono[j*4+t] = 4*(lane+j*32)+t
    const float4* srow4 = (const float4*)(g_score + (size_t)(b * NN + n) * NN);
    unsigned mono_[24];
#pragma unroll
    for (int j = 0; j < 6; j++) {
        float4 f = srow4[lane + j * 32];
        float fv[4] = {f.x, f.y, f.z, f.w};
#pragma unroll
        for (int t = 0; t < 4; t++) {
            unsigned u = __float_as_uint(fv[t]);
            mono_[j * 4 + t] = (u & 0x80000000u) ? ~u : (u | 0x80000000u);
        }
    }
    // cached local max (strict > over ascending local idx -> lowest-index tie)
    unsigned bm = 0u;
    int bidx = -1;
#pragma unroll
    for (int q = 0; q < 24; q++) {
        if (mono_[q] > bm) { bm = mono_[q]; bidx = 4 * (lane + (q >> 2) * 32) + (q & 3); }
    }

    // n-side vectors for this point
    size_t nbase = ((size_t)(b * NN + n) * 32 + lane) * 12;
    const float4* nb4 = (const float4*)(g_nb + nbase);
    float4 n0 = nb4[0], n1 = nb4[1], n2 = nb4[2];
    float nbv[12] = {n0.x, n0.y, n0.z, n0.w, n1.x, n1.y, n1.z, n1.w,
                     n2.x, n2.y, n2.z, n2.w};

    float aK[3] = {}, aV[3] = {};
#pragma unroll
    for (int it = 0; it < 16; it++) {
        unsigned wm = __reduce_max_sync(0xffffffffu, bm);
        unsigned cand = (bm == wm) ? (unsigned)bidx : 0xffffffffu;
        unsigned wi = __reduce_min_sync(0xffffffffu, cand);
        int m = (int)wi;
        // owning lane removes element and rescans its 24
        if (bidx == m) {
            bm = 0u; bidx = -1;
#pragma unroll
            for (int q = 0; q < 24; q++) {
                int gq = 4 * (lane + (q >> 2) * 32) + (q & 3);
                if (gq == m) mono_[q] = 0u;
                if (mono_[q] > bm) { bm = mono_[q]; bidx = gq; }
            }
        }
        // process neighbor m
        size_t mbase = ((size_t)(b * NN + m) * 32 + lane) * 12;
        const float4* mb4 = (const float4*)(g_mb + mbase);
        float4 m0 = mb4[0], m1 = mb4[1], m2 = mb4[2];
        float mb[12] = {m0.x, m0.y, m0.z, m0.w, m1.x, m1.y, m1.z, m1.w,
                        m2.x, m2.y, m2.z, m2.w};
        float Kp[3], Kd[3], Vp[3], Vd[3];
#pragma unroll
        for (int d = 0; d < 3; d++) {
            Kp[d] = mb[d] + nbv[d];
            Kd[d] = mb[3 + d] + nbv[3 + d];
            Vp[d] = mb[6 + d] + nbv[6 + d];
            Vd[d] = mb[9 + d] + nbv[9 + d];
        }
        float dot = Kp[0] * Kd[0] + Kp[1] * Kd[1] + Kp[2] * Kd[2];
        float dsq = Kd[0] * Kd[0] + Kd[1] * Kd[1] + Kd[2] * Kd[2];
        if (dot < 0.f) {
            float f = NEG08 * dot / (dsq + EPSV);
            Kp[0] -= f * Kd[0]; Kp[1] -= f * Kd[1]; Kp[2] -= f * Kd[2];
        }
        float nsq = Kp[0] * Kp[0] + Kp[1] * Kp[1] + Kp[2] * Kp[2];
        float nrm = sqrtf(nsq);
        float chsq = nsq;
#pragma unroll
        for (int off = 16; off; off >>= 1)
            chsq += __shfl_xor_sync(0xffffffffu, chsq, off);
        float chn = sqrtf(chsq);
        float fac = (nrm / fmaxf(nrm, FEPS)) / fmaxf(chn, FEPS);
        aK[0] += Kp[0] * fac; aK[1] += Kp[1] * fac; aK[2] += Kp[2] * fac;

        float dotv = Vp[0] * Vd[0] + Vp[1] * Vd[1] + Vp[2] * Vd[2];
        float dsqv = Vd[0] * Vd[0] + Vd[1] * Vd[1] + Vd[2] * Vd[2];
        if (dotv < 0.f) {
            float f = NEG08 * dotv / (dsqv + EPSV);
            Vp[0] -= f * Vd[0]; Vp[1] -= f * Vd[1]; Vp[2] -= f * Vd[2];
        }
        aV[0] += Vp[0]; aV[1] += Vp[1]; aV[2] += Vp[2];
    }
#pragma unroll
    for (int d = 0; d < 3; d++) {
        g_ksum[(b * 96 + lane * 3 + d) * NN + n] = aK[d];
        g_vsum[(b * 96 + lane * 3 + d) * NN + n] = aV[d];
    }
}

// ---------------- kernel 4a: moment partials --------------------------------
// grid 384 = row*2+half, block 128; thread handles 3 m's of its half (384 wide).
__global__ void moments_kernel() {
    __shared__ float s_part[4][30];
    int blk = blockIdx.x, tid = threadIdx.x;
    int row = blk >> 1, half = blk & 1;
    int wid = tid >> 5, lane = tid & 31;
    size_t base = (size_t)row * NN + half * 384;

    float Kv[3], Vv[3];
#pragma unroll
    for (int j = 0; j < 3; j++) {
        int m = tid + j * 128;
        Kv[j] = g_ksum[base + m];
        Vv[j] = g_vsum[base + m];
    }
    float M[15], G[15];
    float p0 = 1.f, p1 = 1.f, p2 = 1.f;
#pragma unroll
    for (int jj = 0; jj < 15; jj++) {
        M[jj] = (p0 + p1) + p2;
        G[jj] = fmaf(Vv[0], p0, fmaf(Vv[1], p1, Vv[2] * p2));
        p0 *= Kv[0]; p1 *= Kv[1]; p2 *= Kv[2];
    }
#pragma unroll
    for (int jj = 0; jj < 15; jj++) {
#pragma unroll
        for (int off = 16; off; off >>= 1) {
            M[jj] += __shfl_xor_sync(0xffffffffu, M[jj], off);
            G[jj] += __shfl_xor_sync(0xffffffffu, G[jj], off);
        }
    }
    if (lane == 0) {
#pragma unroll
        for (int jj = 0; jj < 15; jj++) {
            s_part[wid][jj] = M[jj];
            s_part[wid][15 + jj] = G[jj];
        }
    }
    __syncthreads();
    if (tid < 30) {
        float s = s_part[0][tid] + s_part[1][tid] + s_part[2][tid] + s_part[3][tid];
        g_part[blk * 32 + tid] = s;
    }
}

// ---------------- kernel 4b: evaluate rank-1 softmax -----------------------
// grid 576 (row = blk/3, seg = blk%3), block 256.
__global__ void eval_kernel(const float* __restrict__ x,
                            float* __restrict__ out) {
    __shared__ float sMo[15], sGo[15];
    int blk = blockIdx.x, tid = threadIdx.x;
    int row = blk / 3, seg = blk % 3;
    if (tid < 30) {
        float s = g_part[(row * 2) * 32 + tid] + g_part[(row * 2 + 1) * 32 + tid];
        if (tid < 15) sMo[tid] = s * c_invf[tid];
        else sGo[tid - 15] = s * c_invf[tid - 15];
    }
    __syncthreads();
    float cM[15], cG[15];
#pragma unroll
    for (int jj = 0; jj < 15; jj++) { cM[jj] = sMo[jj]; cG[jj] = sGo[jj]; }

    size_t idx = (size_t)row * NN + seg * 256 + tid;
    const float scale = 0.10206207262f;  // 1/sqrt(96)
    float t = g_qx[idx] * scale;
    float den = cM[14], num = cG[14];
#pragma unroll
    for (int jj = 13; jj >= 0; jj--) {
        den = fmaf(den, t, cM[jj]);
        num = fmaf(num, t, cG[jj]);
    }
    out[idx] = x[idx] + num / den;
}

// ---------------- launcher --------------------------------------------------
extern "C" void kernel_launch(void* const* d_in, const int* in_sizes, int n_in,
                              void* d_out, int out_size) {
    const float* x   = (const float*)d_in[0];
    const float* y   = (const float*)d_in[1];
    const float* Wqf = (const float*)d_in[2];
    const float* Wqd = (const float*)d_in[3];
    const float* Wkf = (const float*)d_in[4];
    const float* Wkd = (const float*)d_in[5];
    const float* Wvf = (const float*)d_in[6];
    const float* Wvd = (const float*)d_in[7];
    float* out = (float*)d_out;

    pre_kernel<<<384, 128>>>(x, y, Wqf, Wqd, Wkf, Wkd, Wvf, Wvd);
    gram_kernel<<<dim3(12, 12, NB), dim3(16, 16)>>>(y);
    knn_kernel<<<384, 128>>>();
    moments_kernel<<<384, 128>>>();
    eval_kernel<<<576, 256>>>(x, out);
}

// round 5
// speedup vs baseline: 7.5979x; 1.0412x over previous
#include <cuda_runtime.h>
#include <math.h>

#define NB 2
#define NN 768
#define GRID 384
#define TPB 128
#define NEG08 0.8f
#define EPSV 1e-6f
#define FEPS 1e-12f

// ---------------- scratch (device globals) ---------------------------------
__device__ float g_qx[NB * 96 * NN];        // Qx   [row][n]
__device__ float g_score[NB * NN * NN];     // 2*inner - sq[m]
__device__ float g_mb[NB * NN * 32 * 12];   // m-side: [point][o][12]
__device__ float g_nb[NB * NN * 32 * 12];   // n-side
__device__ float g_ksum[NB * 96 * NN];      // [row][n]
__device__ float g_vsum[NB * 96 * NN];
__device__ float g_part[192 * 2 * 32];      // moment partials
__device__ unsigned g_barcnt;               // monotonic barrier counter

__constant__ float c_invf[15] = {
    1.0f, 1.0f, 0.5f, 1.6666666667e-1f, 4.1666666667e-2f, 8.3333333333e-3f,
    1.3888888889e-3f, 1.9841269841e-4f, 2.4801587302e-5f, 2.7557319224e-6f,
    2.7557319224e-7f, 2.5052108385e-8f, 2.0876756988e-9f, 1.6059043837e-10f,
    1.1470745598e-11f};

// ---------------- software grid barrier (all 384 blocks co-resident) -------
__device__ __forceinline__ void grid_bar() {
    __syncthreads();
    __threadfence();
    if (threadIdx.x == 0) {
        unsigned ticket = atomicAdd(&g_barcnt, 1u);
        unsigned target = (ticket / GRID + 1u) * GRID;
        while (atomicAdd(&g_barcnt, 0u) < target) __nanosleep(64);
        __threadfence();
    }
    __syncthreads();
}

// ---------------- phase 1a: gram tile (64n x 64m), 128 threads -------------
__device__ void gram_unit(int u, const float* __restrict__ y,
                          unsigned char* sm) {
    float (*As)[64] = (float (*)[64])sm;
    float (*Bs)[64] = (float (*)[64])(sm + 8192);
    int b = u / 144, rmod = u % 144;
    int n0 = (rmod / 12) * 64, m0 = (rmod % 12) * 64;
    int tid = threadIdx.x;
    int tx = tid & 15, ty = tid >> 4;
    float acc[8][4] = {};
    float bsq[4] = {};
    for (int jc = 0; jc < 96; jc += 32) {
        __syncthreads();
        for (int e = tid; e < 2048; e += TPB) {
            int kk = e >> 6, rr = e & 63;
            As[kk][rr] = y[(b * 96 + jc + kk) * NN + n0 + rr];
            Bs[kk][rr] = y[(b * 96 + jc + kk) * NN + m0 + rr];
        }
        __syncthreads();
#pragma unroll
        for (int kk = 0; kk < 32; kk++) {
            float4 b4 = *(float4*)&Bs[kk][tx * 4];
            float bv[4] = {b4.x, b4.y, b4.z, b4.w};
            float4 a0 = *(float4*)&As[kk][ty * 8];
            float4 a1 = *(float4*)&As[kk][ty * 8 + 4];
            float av[8] = {a0.x, a0.y, a0.z, a0.w, a1.x, a1.y, a1.z, a1.w};
#pragma unroll
            for (int j = 0; j < 4; j++) bsq[j] = fmaf(bv[j], bv[j], bsq[j]);
#pragma unroll
            for (int i = 0; i < 8; i++)
#pragma unroll
                for (int j = 0; j < 4; j++)
                    acc[i][j] = fmaf(av[i], bv[j], acc[i][j]);
        }
    }
#pragma unroll
    for (int i = 0; i < 8; i++) {
        int n = n0 + ty * 8 + i;
        float4 o;
        o.x = 2.f * acc[i][0] - bsq[0];
        o.y = 2.f * acc[i][1] - bsq[1];
        o.z = 2.f * acc[i][2] - bsq[2];
        o.w = 2.f * acc[i][3] - bsq[3];
        *(float4*)&g_score[((size_t)(b * NN + n)) * NN + m0 + tx * 4] = o;
    }
}

// ---------------- phase 1b: per-point precompute (warp per point) ----------
__device__ void pre_unit(int p, const float* __restrict__ x,
                         const float* __restrict__ y,
                         const float* __restrict__ Wqf,
                         const float* __restrict__ Wqd,
                         const float* __restrict__ Wkf,
                         const float* __restrict__ Wkd,
                         const float* __restrict__ Wvf,
                         const float* __restrict__ Wvd,
                         unsigned char* sm) {
    float2 (*sQ)[32] = (float2 (*)[32])sm;                 // 8KB
    float4 (*sM)[32] = (float4 (*)[32])(sm + 8192);        // 16KB
    float4 (*sN)[32] = (float4 (*)[32])(sm + 24576);       // 16KB
    float (*xs)[96]  = (float (*)[96])(sm + 40960);        // 1.5KB
    float (*ys)[96]  = (float (*)[96])(sm + 42496);        // 1.5KB
    int tid = threadIdx.x;
    for (int i = tid; i < 1024; i += TPB) {
        int o = i >> 5, c = i & 31;
        sQ[c][o] = make_float2(Wqf[i], Wqd[i]);
        float kfl = Wkf[o * 64 + c], kdl = Wkd[o * 64 + c];
        float vfl = Wvf[o * 64 + c], vdl = Wvd[o * 64 + c];
        sM[c][o] = make_float4(kfl, kdl, vfl, vdl);
        sN[c][o] = make_float4(Wkf[o * 64 + 32 + c] - kfl,
                               Wkd[o * 64 + 32 + c] - kdl,
                               Wvf[o * 64 + 32 + c] - vfl,
                               Wvd[o * 64 + 32 + c] - vdl);
    }
    int wid = tid >> 5, lane = tid & 31;
    int pt = p * 4 + wid;
    int b = pt / NN, n = pt % NN;
    for (int e = lane; e < 96; e += 32) {
        xs[wid][e] = x[(b * 96 + e) * NN + n];
        ys[wid][e] = y[(b * 96 + e) * NN + n];
    }
    __syncthreads();

    float qp[3] = {}, qd[3] = {};
    float am[4][3] = {}, an[4][3] = {};
#pragma unroll
    for (int c = 0; c < 32; c++) {
        float2 q = sQ[c][lane];
        float4 mv = sM[c][lane];
        float4 nv = sN[c][lane];
        float mvv[4] = {mv.x, mv.y, mv.z, mv.w};
        float nvv[4] = {nv.x, nv.y, nv.z, nv.w};
#pragma unroll
        for (int d = 0; d < 3; d++) {
            float xv = xs[wid][c * 3 + d];
            float yv = ys[wid][c * 3 + d];
            qp[d] = fmaf(q.x, xv, qp[d]);
            qd[d] = fmaf(q.y, xv, qd[d]);
#pragma unroll
            for (int a = 0; a < 4; a++) {
                am[a][d] = fmaf(mvv[a], yv, am[a][d]);
                an[a][d] = fmaf(nvv[a], yv, an[a][d]);
            }
        }
    }
    float dot = qp[0] * qd[0] + qp[1] * qd[1] + qp[2] * qd[2];
    float dsq = qd[0] * qd[0] + qd[1] * qd[1] + qd[2] * qd[2];
    if (dot < 0.f) {
        float f = NEG08 * dot / (dsq + EPSV);
        qp[0] -= f * qd[0]; qp[1] -= f * qd[1]; qp[2] -= f * qd[2];
    }
    float nsq = qp[0] * qp[0] + qp[1] * qp[1] + qp[2] * qp[2];
    float nrm = sqrtf(nsq);
    float chsq = nsq;
#pragma unroll
    for (int off = 16; off; off >>= 1)
        chsq += __shfl_xor_sync(0xffffffffu, chsq, off);
    float chn = sqrtf(chsq);
    float fac = (nrm / fmaxf(nrm, FEPS)) / fmaxf(chn, FEPS);
#pragma unroll
    for (int d = 0; d < 3; d++)
        g_qx[(b * 96 + lane * 3 + d) * NN + n] = qp[d] * fac;

    size_t base = ((size_t)(b * NN + n) * 32 + lane) * 12;
    float4* mb4 = (float4*)(g_mb + base);
    float4* nb4 = (float4*)(g_nb + base);
    mb4[0] = make_float4(am[0][0], am[0][1], am[0][2], am[1][0]);
    mb4[1] = make_float4(am[1][1], am[1][2], am[2][0], am[2][1]);
    mb4[2] = make_float4(am[2][2], am[3][0], am[3][1], am[3][2]);
    nb4[0] = make_float4(an[0][0], an[0][1], an[0][2], an[1][0]);
    nb4[1] = make_float4(an[1][1], an[1][2], an[2][0], an[2][1]);
    nb4[2] = make_float4(an[2][2], an[3][0], an[3][1], an[3][2]);
}

// ---------------- phase 2: warp-per-point top-16 + K/V sums ----------------
__device__ void knn_phase() {
    int tid = threadIdx.x;
    int wid = tid >> 5, lane = tid & 31;
    int pt = blockIdx.x * 4 + wid;
    int b = pt / NN, n = pt % NN;

    const float4* srow4 = (const float4*)(g_score + (size_t)(b * NN + n) * NN);
    unsigned mono_[24];
#pragma unroll
    for (int j = 0; j < 6; j++) {
        float4 f = srow4[lane + j * 32];
        float fv[4] = {f.x, f.y, f.z, f.w};
#pragma unroll
        for (int t = 0; t < 4; t++) {
            unsigned uu = __float_as_uint(fv[t]);
            mono_[j * 4 + t] = (uu & 0x80000000u) ? ~uu : (uu | 0x80000000u);
        }
    }
    unsigned bm = 0u;
    int bidx = -1;
#pragma unroll
    for (int q = 0; q < 24; q++) {
        if (mono_[q] > bm) { bm = mono_[q]; bidx = 4 * (lane + (q >> 2) * 32) + (q & 3); }
    }

    size_t nbase = ((size_t)(b * NN + n) * 32 + lane) * 12;
    const float4* nb4 = (const float4*)(g_nb + nbase);
    float4 n0 = nb4[0], n1 = nb4[1], n2 = nb4[2];
    float nbv[12] = {n0.x, n0.y, n0.z, n0.w, n1.x, n1.y, n1.z, n1.w,
                     n2.x, n2.y, n2.z, n2.w};

    float aK[3] = {}, aV[3] = {};
#pragma unroll
    for (int it = 0; it < 16; it++) {
        unsigned wm = __reduce_max_sync(0xffffffffu, bm);
        unsigned cand = (bm == wm) ? (unsigned)bidx : 0xffffffffu;
        unsigned wi = __reduce_min_sync(0xffffffffu, cand);
        int m = (int)wi;
        if (bidx == m) {
            bm = 0u; bidx = -1;
#pragma unroll
            for (int q = 0; q < 24; q++) {
                int gq = 4 * (lane + (q >> 2) * 32) + (q & 3);
                if (gq == m) mono_[q] = 0u;
                if (mono_[q] > bm) { bm = mono_[q]; bidx = gq; }
            }
        }
        size_t mbase = ((size_t)(b * NN + m) * 32 + lane) * 12;
        const float4* mb4 = (const float4*)(g_mb + mbase);
        float4 m0 = mb4[0], m1 = mb4[1], m2 = mb4[2];
        float mb[12] = {m0.x, m0.y, m0.z, m0.w, m1.x, m1.y, m1.z, m1.w,
                        m2.x, m2.y, m2.z, m2.w};
        float Kp[3], Kd[3], Vp[3], Vd[3];
#pragma unroll
        for (int d = 0; d < 3; d++) {
            Kp[d] = mb[d] + nbv[d];
            Kd[d] = mb[3 + d] + nbv[3 + d];
            Vp[d] = mb[6 + d] + nbv[6 + d];
            Vd[d] = mb[9 + d] + nbv[9 + d];
        }
        float dot = Kp[0] * Kd[0] + Kp[1] * Kd[1] + Kp[2] * Kd[2];
        float dsq = Kd[0] * Kd[0] + Kd[1] * Kd[1] + Kd[2] * Kd[2];
        if (dot < 0.f) {
            float f = NEG08 * dot / (dsq + EPSV);
            Kp[0] -= f * Kd[0]; Kp[1] -= f * Kd[1]; Kp[2] -= f * Kd[2];
        }
        float nsq = Kp[0] * Kp[0] + Kp[1] * Kp[1] + Kp[2] * Kp[2];
        float nrm = sqrtf(nsq);
        float chsq = nsq;
#pragma unroll
        for (int off = 16; off; off >>= 1)
            chsq += __shfl_xor_sync(0xffffffffu, chsq, off);
        float chn = sqrtf(chsq);
        float fac = (nrm / fmaxf(nrm, FEPS)) / fmaxf(chn, FEPS);
        aK[0] += Kp[0] * fac; aK[1] += Kp[1] * fac; aK[2] += Kp[2] * fac;

        float dotv = Vp[0] * Vd[0] + Vp[1] * Vd[1] + Vp[2] * Vd[2];
        float dsqv = Vd[0] * Vd[0] + Vd[1] * Vd[1] + Vd[2] * Vd[2];
        if (dotv < 0.f) {
            float f = NEG08 * dotv / (dsqv + EPSV);
            Vp[0] -= f * Vd[0]; Vp[1] -= f * Vd[1]; Vp[2] -= f * Vd[2];
        }
        aV[0] += Vp[0]; aV[1] += Vp[1]; aV[2] += Vp[2];
    }
#pragma unroll
    for (int d = 0; d < 3; d++) {
        g_ksum[(b * 96 + lane * 3 + d) * NN + n] = aK[d];
        g_vsum[(b * 96 + lane * 3 + d) * NN + n] = aV[d];
    }
}

// ---------------- phase 3: moment partials ---------------------------------
__device__ void moments_phase(unsigned char* sm) {
    float (*s_part)[30] = (float (*)[30])sm;
    int blk = blockIdx.x, tid = threadIdx.x;
    int row = blk >> 1, half = blk & 1;
    int wid = tid >> 5, lane = tid & 31;
    size_t base = (size_t)row * NN + half * 384;

    float Kv[3], Vv[3];
#pragma unroll
    for (int j = 0; j < 3; j++) {
        int m = tid + j * 128;
        Kv[j] = g_ksum[base + m];
        Vv[j] = g_vsum[base + m];
    }
    float M[15], G[15];
    float p0 = 1.f, p1 = 1.f, p2 = 1.f;
#pragma unroll
    for (int jj = 0; jj < 15; jj++) {
        M[jj] = (p0 + p1) + p2;
        G[jj] = fmaf(Vv[0], p0, fmaf(Vv[1], p1, Vv[2] * p2));
        p0 *= Kv[0]; p1 *= Kv[1]; p2 *= Kv[2];
    }
#pragma unroll
    for (int jj = 0; jj < 15; jj++) {
#pragma unroll
        for (int off = 16; off; off >>= 1) {
            M[jj] += __shfl_xor_sync(0xffffffffu, M[jj], off);
            G[jj] += __shfl_xor_sync(0xffffffffu, G[jj], off);
        }
    }
    if (lane == 0) {
#pragma unroll
        for (int jj = 0; jj < 15; jj++) {
            s_part[wid][jj] = M[jj];
            s_part[wid][15 + jj] = G[jj];
        }
    }
    __syncthreads();
    if (tid < 30) {
        float s = s_part[0][tid] + s_part[1][tid] + s_part[2][tid] + s_part[3][tid];
        g_part[blk * 32 + tid] = s;
    }
}

// ---------------- phase 4: evaluate rank-1 softmax -------------------------
__device__ void eval_phase(const float* __restrict__ x,
                           float* __restrict__ out, unsigned char* sm) {
    float* sMo = (float*)sm;
    float* sGo = (float*)sm + 16;
    int blk = blockIdx.x, tid = threadIdx.x;
    int row = blk >> 1, half = blk & 1;
    if (tid < 30) {
        float s = g_part[(row * 2) * 32 + tid] + g_part[(row * 2 + 1) * 32 + tid];
        if (tid < 15) sMo[tid] = s * c_invf[tid];
        else sGo[tid - 15] = s * c_invf[tid - 15];
    }
    __syncthreads();
    float cM[15], cG[15];
#pragma unroll
    for (int jj = 0; jj < 15; jj++) { cM[jj] = sMo[jj]; cG[jj] = sGo[jj]; }

    const float scale = 0.10206207262f;  // 1/sqrt(96)
#pragma unroll
    for (int j = 0; j < 3; j++) {
        size_t idx = (size_t)row * NN + half * 384 + tid + j * 128;
        float t = g_qx[idx] * scale;
        float den = cM[14], num = cG[14];
#pragma unroll
        for (int jj = 13; jj >= 0; jj--) {
            den = fmaf(den, t, cM[jj]);
            num = fmaf(num, t, cG[jj]);
        }
        out[idx] = x[idx] + num / den;
    }
}

// ---------------- fused mega-kernel ----------------------------------------
__global__ void __launch_bounds__(TPB)
fused_kernel(const float* __restrict__ x, const float* __restrict__ y,
             const float* __restrict__ Wqf, const float* __restrict__ Wqd,
             const float* __restrict__ Wkf, const float* __restrict__ Wkd,
             const float* __restrict__ Wvf, const float* __restrict__ Wvd,
             float* __restrict__ out) {
    __shared__ __align__(16) unsigned char sm[44032];

    // phase 1: gram tiles (units 0..287) + per-point precompute (288..671)
    for (int u = blockIdx.x; u < 672; u += GRID) {
        if (u < 288) gram_unit(u, y, sm);
        else pre_unit(u - 288, x, y, Wqf, Wqd, Wkf, Wkd, Wvf, Wvd, sm);
        __syncthreads();
    }
    grid_bar();
    knn_phase();
    grid_bar();
    moments_phase(sm);
    grid_bar();
    eval_phase(x, out, sm);
}

// ---------------- launcher --------------------------------------------------
extern "C" void kernel_launch(void* const* d_in, const int* in_sizes, int n_in,
                              void* d_out, int out_size) {
    const float* x   = (const float*)d_in[0];
    const float* y   = (const float*)d_in[1];
    const float* Wqf = (const float*)d_in[2];
    const float* Wqd = (const float*)d_in[3];
    const float* Wkf = (const float*)d_in[4];
    const float* Wkd = (const float*)d_in[5];
    const float* Wvf = (const float*)d_in[6];
    const float* Wvd = (const float*)d_in[7];
    float* out = (float*)d_out;

    fused_kernel<<<GRID, TPB>>>(x, y, Wqf, Wqd, Wkf, Wkd, Wvf, Wvd, out);
}

// round 6
// speedup vs baseline: 7.9301x; 1.0437x over previous
#include <cuda_runtime.h>
#include <math.h>

#define NB 2
#define NN 768
#define GRID 576
#define TPB 128
#define NEG08 0.8f
#define EPSV 1e-6f
#define FEPS 1e-12f

// ---------------- scratch (device globals) ---------------------------------
__device__ float g_qx[NB * 96 * NN];        // Qx   [row][n]
__device__ float g_score[NB * NN * NN];     // 2*inner - sq[m]
__device__ float g_mb[NB * NN * 32 * 12];   // m-side: [point][o][12]
__device__ float g_nb[NB * NN * 32 * 12];   // n-side
__device__ float g_ksum[NB * 96 * NN];      // [row][n]
__device__ float g_vsum[NB * 96 * NN];
__device__ float g_part[576 * 32];          // moment partials [row*3+third][30]
__device__ unsigned g_barcnt;               // monotonic barrier counter

__constant__ float c_invf[15] = {
    1.0f, 1.0f, 0.5f, 1.6666666667e-1f, 4.1666666667e-2f, 8.3333333333e-3f,
    1.3888888889e-3f, 1.9841269841e-4f, 2.4801587302e-5f, 2.7557319224e-6f,
    2.7557319224e-7f, 2.5052108385e-8f, 2.0876756988e-9f, 1.6059043837e-10f,
    1.1470745598e-11f};

// ---------------- software grid barrier (all 576 blocks co-resident) -------
__device__ __forceinline__ void grid_bar() {
    __syncthreads();
    __threadfence();
    if (threadIdx.x == 0) {
        unsigned ticket = atomicAdd(&g_barcnt, 1u);
        unsigned target = (ticket / GRID + 1u) * GRID;
        while (atomicAdd(&g_barcnt, 0u) < target) __nanosleep(64);
        __threadfence();
    }
    __syncthreads();
}

// ---------------- phase 1a: symmetric gram tile-pair (64x64) ---------------
// unit u in [0,156): b = u/78, pair (i<=j) of 12x12 tile grid.
// Writes score[n][m] = 2*inner - sq[m]; if i!=j also score[m][n] = 2*inner - sq[n].
__device__ void gram_unit(int u, const float* __restrict__ y,
                          unsigned char* sm) {
    float (*As)[64] = (float (*)[64])sm;
    float (*Bs)[64] = (float (*)[64])(sm + 8192);
    int b = u / 78, pr = u % 78;
    int i = 0;
    while (pr >= 12 - i) { pr -= 12 - i; i++; }
    int j = i + pr;
    int n0 = i * 64, m0 = j * 64;
    int tid = threadIdx.x;
    int tx = tid & 15, ty = tid >> 4;
    float acc[8][4] = {};
    float bsq[4] = {}, asq[8] = {};
    for (int jc = 0; jc < 96; jc += 32) {
        __syncthreads();
        for (int e = tid; e < 2048; e += TPB) {
            int kk = e >> 6, rr = e & 63;
            As[kk][rr] = y[(b * 96 + jc + kk) * NN + n0 + rr];
            Bs[kk][rr] = y[(b * 96 + jc + kk) * NN + m0 + rr];
        }
        __syncthreads();
#pragma unroll
        for (int kk = 0; kk < 32; kk++) {
            float4 b4 = *(float4*)&Bs[kk][tx * 4];
            float bv[4] = {b4.x, b4.y, b4.z, b4.w};
            float4 a0 = *(float4*)&As[kk][ty * 8];
            float4 a1 = *(float4*)&As[kk][ty * 8 + 4];
            float av[8] = {a0.x, a0.y, a0.z, a0.w, a1.x, a1.y, a1.z, a1.w};
#pragma unroll
            for (int q = 0; q < 4; q++) bsq[q] = fmaf(bv[q], bv[q], bsq[q]);
#pragma unroll
            for (int q = 0; q < 8; q++) asq[q] = fmaf(av[q], av[q], asq[q]);
#pragma unroll
            for (int p = 0; p < 8; p++)
#pragma unroll
                for (int q = 0; q < 4; q++)
                    acc[p][q] = fmaf(av[p], bv[q], acc[p][q]);
        }
    }
#pragma unroll
    for (int p = 0; p < 8; p++) {
        int n = n0 + ty * 8 + p;
        float4 o;
        o.x = 2.f * acc[p][0] - bsq[0];
        o.y = 2.f * acc[p][1] - bsq[1];
        o.z = 2.f * acc[p][2] - bsq[2];
        o.w = 2.f * acc[p][3] - bsq[3];
        *(float4*)&g_score[((size_t)(b * NN + n)) * NN + m0 + tx * 4] = o;
    }
    if (i != j) {
#pragma unroll
        for (int q = 0; q < 4; q++) {
            int m = m0 + tx * 4 + q;
            float4 o1, o2;
            o1.x = 2.f * acc[0][q] - asq[0];
            o1.y = 2.f * acc[1][q] - asq[1];
            o1.z = 2.f * acc[2][q] - asq[2];
            o1.w = 2.f * acc[3][q] - asq[3];
            o2.x = 2.f * acc[4][q] - asq[4];
            o2.y = 2.f * acc[5][q] - asq[5];
            o2.z = 2.f * acc[6][q] - asq[6];
            o2.w = 2.f * acc[7][q] - asq[7];
            size_t rb = ((size_t)(b * NN + m)) * NN + n0 + ty * 8;
            *(float4*)&g_score[rb] = o1;
            *(float4*)&g_score[rb + 4] = o2;
        }
    }
}

// ---------------- phase 1b: per-point precompute (warp per point) ----------
__device__ void pre_unit(int p, const float* __restrict__ x,
                         const float* __restrict__ y,
                         const float* __restrict__ Wqf,
                         const float* __restrict__ Wqd,
                         const float* __restrict__ Wkf,
                         const float* __restrict__ Wkd,
                         const float* __restrict__ Wvf,
                         const float* __restrict__ Wvd,
                         unsigned char* sm) {
    float2 (*sQ)[32] = (float2 (*)[32])sm;                 // 8KB
    float4 (*sM)[32] = (float4 (*)[32])(sm + 8192);        // 16KB
    float4 (*sN)[32] = (float4 (*)[32])(sm + 24576);       // 16KB
    float (*xs)[96]  = (float (*)[96])(sm + 40960);        // 1.5KB
    float (*ys)[96]  = (float (*)[96])(sm + 42496);        // 1.5KB
    int tid = threadIdx.x;
    for (int q = tid; q < 1024; q += TPB) {
        int o = q >> 5, c = q & 31;
        sQ[c][o] = make_float2(Wqf[q], Wqd[q]);
        float kfl = Wkf[o * 64 + c], kdl = Wkd[o * 64 + c];
        float vfl = Wvf[o * 64 + c], vdl = Wvd[o * 64 + c];
        sM[c][o] = make_float4(kfl, kdl, vfl, vdl);
        sN[c][o] = make_float4(Wkf[o * 64 + 32 + c] - kfl,
                               Wkd[o * 64 + 32 + c] - kdl,
                               Wvf[o * 64 + 32 + c] - vfl,
                               Wvd[o * 64 + 32 + c] - vdl);
    }
    int wid = tid >> 5, lane = tid & 31;
    int pt = p * 4 + wid;
    int b = pt / NN, n = pt % NN;
    for (int e = lane; e < 96; e += 32) {
        xs[wid][e] = x[(b * 96 + e) * NN + n];
        ys[wid][e] = y[(b * 96 + e) * NN + n];
    }
    __syncthreads();

    float qp[3] = {}, qd[3] = {};
    float am[4][3] = {}, an[4][3] = {};
#pragma unroll
    for (int c = 0; c < 32; c++) {
        float2 q = sQ[c][lane];
        float4 mv = sM[c][lane];
        float4 nv = sN[c][lane];
        float mvv[4] = {mv.x, mv.y, mv.z, mv.w};
        float nvv[4] = {nv.x, nv.y, nv.z, nv.w};
#pragma unroll
        for (int d = 0; d < 3; d++) {
            float xv = xs[wid][c * 3 + d];
            float yv = ys[wid][c * 3 + d];
            qp[d] = fmaf(q.x, xv, qp[d]);
            qd[d] = fmaf(q.y, xv, qd[d]);
#pragma unroll
            for (int a = 0; a < 4; a++) {
                am[a][d] = fmaf(mvv[a], yv, am[a][d]);
                an[a][d] = fmaf(nvv[a], yv, an[a][d]);
            }
        }
    }
    float dot = qp[0] * qd[0] + qp[1] * qd[1] + qp[2] * qd[2];
    float dsq = qd[0] * qd[0] + qd[1] * qd[1] + qd[2] * qd[2];
    if (dot < 0.f) {
        float f = NEG08 * dot / (dsq + EPSV);
        qp[0] -= f * qd[0]; qp[1] -= f * qd[1]; qp[2] -= f * qd[2];
    }
    float nsq = qp[0] * qp[0] + qp[1] * qp[1] + qp[2] * qp[2];
    float nrm = sqrtf(nsq);
    float chsq = nsq;
#pragma unroll
    for (int off = 16; off; off >>= 1)
        chsq += __shfl_xor_sync(0xffffffffu, chsq, off);
    float chn = sqrtf(chsq);
    float fac = (nrm / fmaxf(nrm, FEPS)) / fmaxf(chn, FEPS);
#pragma unroll
    for (int d = 0; d < 3; d++)
        g_qx[(b * 96 + lane * 3 + d) * NN + n] = qp[d] * fac;

    size_t base = ((size_t)(b * NN + n) * 32 + lane) * 12;
    float4* mb4 = (float4*)(g_mb + base);
    float4* nb4 = (float4*)(g_nb + base);
    mb4[0] = make_float4(am[0][0], am[0][1], am[0][2], am[1][0]);
    mb4[1] = make_float4(am[1][1], am[1][2], am[2][0], am[2][1]);
    mb4[2] = make_float4(am[2][2], am[3][0], am[3][1], am[3][2]);
    nb4[0] = make_float4(an[0][0], an[0][1], an[0][2], an[1][0]);
    nb4[1] = make_float4(an[1][1], an[1][2], an[2][0], an[2][1]);
    nb4[2] = make_float4(an[2][2], an[3][0], an[3][1], an[3][2]);
}

// ---------------- phase 2: warp-per-point top-16 + K/V sums ----------------
__device__ void knn_phase() {
    int tid = threadIdx.x;
    int wid = tid >> 5, lane = tid & 31;
    int gw = blockIdx.x * 4 + wid;
    if (gw >= NB * NN) return;
    int b = gw / NN, n = gw % NN;

    const float4* srow4 = (const float4*)(g_score + (size_t)(b * NN + n) * NN);
    unsigned mono_[24];
#pragma unroll
    for (int j = 0; j < 6; j++) {
        float4 f = srow4[lane + j * 32];
        float fv[4] = {f.x, f.y, f.z, f.w};
#pragma unroll
        for (int t = 0; t < 4; t++) {
            unsigned uu = __float_as_uint(fv[t]);
            mono_[j * 4 + t] = (uu & 0x80000000u) ? ~uu : (uu | 0x80000000u);
        }
    }
    // n-side vectors (load early, overlaps with selection)
    size_t nbase = ((size_t)(b * NN + n) * 32 + lane) * 12;
    const float4* nb4 = (const float4*)(g_nb + nbase);
    float4 nv0 = nb4[0], nv1 = nb4[1], nv2 = nb4[2];
    float nbv[12] = {nv0.x, nv0.y, nv0.z, nv0.w, nv1.x, nv1.y, nv1.z, nv1.w,
                     nv2.x, nv2.y, nv2.z, nv2.w};

    unsigned bm = 0u;
    int bidx = -1;
#pragma unroll
    for (int q = 0; q < 24; q++) {
        if (mono_[q] > bm) { bm = mono_[q]; bidx = 4 * (lane + (q >> 2) * 32) + (q & 3); }
    }

    // ---- selection: collect all 16 indices first ----
    int msel[16];
#pragma unroll
    for (int it = 0; it < 16; it++) {
        unsigned wm = __reduce_max_sync(0xffffffffu, bm);
        unsigned cand = (bm == wm) ? (unsigned)bidx : 0xffffffffu;
        unsigned wi = __reduce_min_sync(0xffffffffu, cand);
        int m = (int)wi;
        msel[it] = m;
        if (bidx == m) {
            bm = 0u; bidx = -1;
#pragma unroll
            for (int q = 0; q < 24; q++) {
                int gq = 4 * (lane + (q >> 2) * 32) + (q & 3);
                if (gq == m) mono_[q] = 0u;
                if (mono_[q] > bm) { bm = mono_[q]; bidx = gq; }
            }
        }
    }

    // ---- process neighbors in groups of 4 (batched loads, ILP compute) ----
    float aK[3] = {}, aV[3] = {};
#pragma unroll
    for (int g = 0; g < 4; g++) {
        float4 v[4][3];
#pragma unroll
        for (int t = 0; t < 4; t++) {
            size_t mbase = ((size_t)(b * NN + msel[g * 4 + t]) * 32 + lane) * 12;
            const float4* mb4 = (const float4*)(g_mb + mbase);
            v[t][0] = mb4[0]; v[t][1] = mb4[1]; v[t][2] = mb4[2];
        }
#pragma unroll
        for (int t = 0; t < 4; t++) {
            float mb[12] = {v[t][0].x, v[t][0].y, v[t][0].z, v[t][0].w,
                            v[t][1].x, v[t][1].y, v[t][1].z, v[t][1].w,
                            v[t][2].x, v[t][2].y, v[t][2].z, v[t][2].w};
            float Kp[3], Kd[3], Vp[3], Vd[3];
#pragma unroll
            for (int d = 0; d < 3; d++) {
                Kp[d] = mb[d] + nbv[d];
                Kd[d] = mb[3 + d] + nbv[3 + d];
                Vp[d] = mb[6 + d] + nbv[6 + d];
                Vd[d] = mb[9 + d] + nbv[9 + d];
            }
            float dot = Kp[0] * Kd[0] + Kp[1] * Kd[1] + Kp[2] * Kd[2];
            float dsq = Kd[0] * Kd[0] + Kd[1] * Kd[1] + Kd[2] * Kd[2];
            if (dot < 0.f) {
                float f = NEG08 * dot / (dsq + EPSV);
                Kp[0] -= f * Kd[0]; Kp[1] -= f * Kd[1]; Kp[2] -= f * Kd[2];
            }
            float nsq = Kp[0] * Kp[0] + Kp[1] * Kp[1] + Kp[2] * Kp[2];
            float nrm = sqrtf(nsq);
            float chsq = nsq;
#pragma unroll
            for (int off = 16; off; off >>= 1)
                chsq += __shfl_xor_sync(0xffffffffu, chsq, off);
            float chn = sqrtf(chsq);
            float fac = (nrm / fmaxf(nrm, FEPS)) / fmaxf(chn, FEPS);
            aK[0] += Kp[0] * fac; aK[1] += Kp[1] * fac; aK[2] += Kp[2] * fac;

            float dotv = Vp[0] * Vd[0] + Vp[1] * Vd[1] + Vp[2] * Vd[2];
            float dsqv = Vd[0] * Vd[0] + Vd[1] * Vd[1] + Vd[2] * Vd[2];
            if (dotv < 0.f) {
                float f = NEG08 * dotv / (dsqv + EPSV);
                Vp[0] -= f * Vd[0]; Vp[1] -= f * Vd[1]; Vp[2] -= f * Vd[2];
            }
            aV[0] += Vp[0]; aV[1] += Vp[1]; aV[2] += Vp[2];
        }
    }
#pragma unroll
    for (int d = 0; d < 3; d++) {
        g_ksum[(b * 96 + lane * 3 + d) * NN + n] = aK[d];
        g_vsum[(b * 96 + lane * 3 + d) * NN + n] = aV[d];
    }
}

// ---------------- phase 3: moment partials (576 units of 256 cols) ---------
__device__ void moments_phase(unsigned char* sm) {
    float (*s_part)[30] = (float (*)[30])sm;
    int u = blockIdx.x, tid = threadIdx.x;
    int row = u / 3, third = u % 3;
    int wid = tid >> 5, lane = tid & 31;
    size_t base = (size_t)row * NN + third * 256;

    float Kv[2], Vv[2];
#pragma unroll
    for (int j = 0; j < 2; j++) {
        int m = tid + j * 128;
        Kv[j] = g_ksum[base + m];
        Vv[j] = g_vsum[base + m];
    }
    float M[15], G[15];
    float p0 = 1.f, p1 = 1.f;
#pragma unroll
    for (int jj = 0; jj < 15; jj++) {
        M[jj] = p0 + p1;
        G[jj] = fmaf(Vv[0], p0, Vv[1] * p1);
        p0 *= Kv[0]; p1 *= Kv[1];
    }
#pragma unroll
    for (int jj = 0; jj < 15; jj++) {
#pragma unroll
        for (int off = 16; off; off >>= 1) {
            M[jj] += __shfl_xor_sync(0xffffffffu, M[jj], off);
            G[jj] += __shfl_xor_sync(0xffffffffu, G[jj], off);
        }
    }
    if (lane == 0) {
#pragma unroll
        for (int jj = 0; jj < 15; jj++) {
            s_part[wid][jj] = M[jj];
            s_part[wid][15 + jj] = G[jj];
        }
    }
    __syncthreads();
    if (tid < 30) {
        float s = s_part[0][tid] + s_part[1][tid] + s_part[2][tid] + s_part[3][tid];
        g_part[u * 32 + tid] = s;
    }
}

// ---------------- phase 4: evaluate rank-1 softmax (576 units) -------------
__device__ void eval_phase(const float* __restrict__ x,
                           float* __restrict__ out, unsigned char* sm) {
    float* sMo = (float*)sm;
    float* sGo = (float*)sm + 16;
    int u = blockIdx.x, tid = threadIdx.x;
    int row = u / 3, third = u % 3;
    if (tid < 30) {
        float s = g_part[(row * 3 + 0) * 32 + tid] +
                  g_part[(row * 3 + 1) * 32 + tid] +
                  g_part[(row * 3 + 2) * 32 + tid];
        if (tid < 15) sMo[tid] = s * c_invf[tid];
        else sGo[tid - 15] = s * c_invf[tid - 15];
    }
    __syncthreads();
    float cM[15], cG[15];
#pragma unroll
    for (int jj = 0; jj < 15; jj++) { cM[jj] = sMo[jj]; cG[jj] = sGo[jj]; }

    const float scale = 0.10206207262f;  // 1/sqrt(96)
#pragma unroll
    for (int j = 0; j < 2; j++) {
        size_t idx = (size_t)row * NN + third * 256 + tid + j * 128;
        float t = g_qx[idx] * scale;
        float den = cM[14], num = cG[14];
#pragma unroll
        for (int jj = 13; jj >= 0; jj--) {
            den = fmaf(den, t, cM[jj]);
            num = fmaf(num, t, cG[jj]);
        }
        out[idx] = x[idx] + num / den;
    }
}

// ---------------- fused mega-kernel ----------------------------------------
__global__ void __launch_bounds__(TPB, 4)
fused_kernel(const float* __restrict__ x, const float* __restrict__ y,
             const float* __restrict__ Wqf, const float* __restrict__ Wqd,
             const float* __restrict__ Wkf, const float* __restrict__ Wkd,
             const float* __restrict__ Wvf, const float* __restrict__ Wvd,
             float* __restrict__ out) {
    __shared__ __align__(16) unsigned char sm[44032];

    // phase 1: one unit per block (156 gram-pairs + 384 pre = 540 units)
    int u = blockIdx.x;
    if (u < 156) gram_unit(u, y, sm);
    else if (u < 540) pre_unit(u - 156, x, y, Wqf, Wqd, Wkf, Wkd, Wvf, Wvd, sm);
    grid_bar();
    knn_phase();
    grid_bar();
    moments_phase(sm);
    grid_bar();
    eval_phase(x, out, sm);
}

// ---------------- launcher --------------------------------------------------
extern "C" void kernel_launch(void* const* d_in, const int* in_sizes, int n_in,
                              void* d_out, int out_size) {
    const float* x   = (const float*)d_in[0];
    const float* y   = (const float*)d_in[1];
    const float* Wqf = (const float*)d_in[2];
    const float* Wqd = (const float*)d_in[3];
    const float* Wkf = (const float*)d_in[4];
    const float* Wkd = (const float*)d_in[5];
    const float* Wvf = (const float*)d_in[6];
    const float* Wvd = (const float*)d_in[7];
    float* out = (float*)d_out;

    fused_kernel<<<GRID, TPB>>>(x, y, Wqf, Wqd, Wkf, Wkd, Wvf, Wvd, out);
}